// round 7
// baseline (speedup 1.0000x reference)
#include <cuda_runtime.h>
#include <cstdint>
#include <math.h>

#define Nn  50000
#define FIN 256
#define Hh  256
#define Ee  400000

// ---------------- scratch (static device globals; no allocation) ----------------
__device__ float g_hr[(size_t)Nn * Hh];     // tf32-pre-rounded GEMM input
__device__ float g_hw[(size_t)Nn * Hh];
__device__ float g_AB[(size_t)Nn * 512];    // xr first, then edge-MLP pre-activations
__device__ float g_ph[(size_t)Nn * (Hh / 2)];
__device__ float g_norm[Nn];
__device__ float g_wt[65536 * 6 + 32768];   // packed/transposed tf32 weights
__device__ float g_b640[640];
// CSR (by dst)
__device__ int   g_deg[Nn];
__device__ int   g_off[Nn + 1];
__device__ int   g_cur[Nn];
__device__ int   g_csrc[Ee];
__device__ int   g_eid[Ee];
__device__ float g_coef[Ee];

// ---------------- PTX helpers (baseline sm_100, no 'a' features) ----------------
__device__ __forceinline__ uint32_t smem_u32(const void* p) {
    uint32_t a;
    asm("{ .reg .u64 t; cvta.to.shared.u64 t, %1; cvt.u32.u64 %0, t; }" : "=r"(a) : "l"(p));
    return a;
}
__device__ __forceinline__ float rna_tf32(float v) {
    uint32_t u;
    asm("cvt.rna.tf32.f32 %0, %1;" : "=r"(u) : "f"(v));
    return __uint_as_float(u);
}
__device__ __forceinline__ uint32_t lds32(uint32_t a) {
    uint32_t v;
    asm volatile("ld.shared.b32 %0, [%1];" : "=r"(v) : "r"(a));
    return v;
}
__device__ __forceinline__ void cp16(uint32_t dst, const void* src) {
    asm volatile("cp.async.cg.shared.global [%0], [%1], 16;" :: "r"(dst), "l"(src) : "memory");
}
__device__ __forceinline__ void cp_commit() {
    asm volatile("cp.async.commit_group;" ::: "memory");
}
__device__ __forceinline__ void cp_wait0() {
    asm volatile("cp.async.wait_group 0;" ::: "memory");
}
__device__ __forceinline__ void cp_wait1() {
    asm volatile("cp.async.wait_group 1;" ::: "memory");
}
__device__ __forceinline__ void mma_tf32(float* c, const uint32_t* a, const uint32_t* b) {
    asm volatile(
        "mma.sync.aligned.m16n8k8.row.col.f32.tf32.tf32.f32 "
        "{%0,%1,%2,%3},{%4,%5,%6,%7},{%8,%9},{%0,%1,%2,%3};"
        : "+f"(c[0]), "+f"(c[1]), "+f"(c[2]), "+f"(c[3])
        : "r"(a[0]), "r"(a[1]), "r"(a[2]), "r"(a[3]), "r"(b[0]), "r"(b[1]));
}
#define SWZ128(o) ((o) ^ (((o) >> 3) & 0x70))

// ---------------- one-shot weight pack (transpose + tf32 round) ----------------
__global__ void pack_all_k(const float* __restrict__ W_in, const float* __restrict__ Wg,
                           const float* __restrict__ Wh1, const float* __restrict__ Wp1,
                           float* __restrict__ wt) {
    int i = blockIdx.x * blockDim.x + threadIdx.x;
    const int T = 65536 * 6 + 32768;
    if (i >= T) return;
    float v;
    if (i < 65536) {
        int n = i >> 8, k = i & 255;
        v = W_in[(size_t)k * 256 + n];
    } else if (i < 4 * 65536) {
        int j = i - 65536;
        int l = j >> 16; j &= 65535;
        int n = j >> 8, k = j & 255;
        v = Wg[(size_t)l * 65536 + (size_t)k * 256 + n];
    } else if (i < 6 * 65536) {
        int j = i - 4 * 65536;
        int half = j >> 16; j &= 65535;
        int n = j >> 8, k = j & 255;
        v = Wh1[(size_t)(half * 256 + k) * 256 + n];
    } else {
        int j = i - 6 * 65536;
        int n = j >> 8, k = j & 255;
        v = Wp1[(size_t)k * 128 + n];
    }
    wt[i] = rna_tf32(v);
}
__global__ void bias640_k(const float* __restrict__ bh1, const float* __restrict__ bp1,
                          float* __restrict__ b640) {
    int i = blockIdx.x * blockDim.x + threadIdx.x;
    if (i >= 640) return;
    b640[i] = (i < 256) ? bh1[i] : (i < 512 ? 0.0f : bp1[i - 512]);
}
__global__ void round_x_k(const float* __restrict__ x, float* __restrict__ xr) {
    int i = blockIdx.x * blockDim.x + threadIdx.x;
    if (i >= Nn * 64) return;
    float4 v = ((const float4*)x)[i];
    v.x = rna_tf32(v.x); v.y = rna_tf32(v.y); v.z = rna_tf32(v.z); v.w = rna_tf32(v.w);
    ((float4*)xr)[i] = v;
}

// ---------------- CSR build ----------------
__global__ void deg_zero_k(int* deg) {
    int i = blockIdx.x * blockDim.x + threadIdx.x;
    if (i < Nn) deg[i] = 0;
}
__global__ void deg_hist_k(const int* __restrict__ dst, int* deg) {
    int e = blockIdx.x * blockDim.x + threadIdx.x;
    if (e < Ee) atomicAdd(&deg[dst[e]], 1);
}
__global__ __launch_bounds__(1024) void scan_k(const int* __restrict__ deg,
                                               int* __restrict__ off, int* __restrict__ cur,
                                               float* __restrict__ nrm) {
    __shared__ int part[1024];
    const int CH = (Nn + 1023) / 1024;
    int t = threadIdx.x;
    int start = t * CH;
    int end = start + CH; if (end > Nn) end = Nn;
    int s = 0;
    for (int i = start; i < end; i++) s += deg[i];
    part[t] = s;
    __syncthreads();
    for (int o = 1; o < 1024; o <<= 1) {
        int v = (t >= o) ? part[t - o] : 0;
        __syncthreads();
        part[t] += v;
        __syncthreads();
    }
    int run = (t > 0) ? part[t - 1] : 0;
    for (int i = start; i < end; i++) {
        int d = deg[i];
        off[i] = run; cur[i] = run;
        nrm[i] = rsqrtf((float)d + 1.0f);
        run += d;
    }
    if (t == 1023) off[Nn] = run;
}
__global__ void fill_k(const int* __restrict__ src, const int* __restrict__ dst,
                       const float* __restrict__ nrm, int* cur,
                       int* __restrict__ csrc, int* __restrict__ eid,
                       float* __restrict__ coef) {
    int e = blockIdx.x * blockDim.x + threadIdx.x;
    if (e >= Ee) return;
    int s = src[e], d = dst[e];
    int pos = atomicAdd(&cur[d], 1);
    csrc[pos] = s;
    eid[pos] = e;
    coef[pos] = nrm[s] * nrm[d];
}

// ---------------- TF32 mma.sync GEMM, CTA 128x256, 512 threads (16 warps) ----------------
// Warp grid 4(M) x 4(N), warp tile 32x64. A pre-rounded tf32. 3-stage cp.async pipe.
// Regs capped at 128/thread -> full 16-warp residency (4 warps/SMSP) for latency hiding.
#define LOAD_FRAGS(kss, AF, BF) do { \
    const int k_ = (kss) * 8 + tig; \
    _Pragma("unroll") \
    for (int mt_ = 0; mt_ < 2; mt_++) { \
        int r0_ = wm * 32 + mt_ * 16 + gid; \
        AF[mt_][0] = lds32(aB + SWZ128((uint32_t)(r0_ * 128 + k_ * 4))); \
        AF[mt_][1] = lds32(aB + SWZ128((uint32_t)((r0_ + 8) * 128 + k_ * 4))); \
        AF[mt_][2] = lds32(aB + SWZ128((uint32_t)(r0_ * 128 + (k_ + 4) * 4))); \
        AF[mt_][3] = lds32(aB + SWZ128((uint32_t)((r0_ + 8) * 128 + (k_ + 4) * 4))); \
    } \
    _Pragma("unroll") \
    for (int nt_ = 0; nt_ < 8; nt_++) { \
        int n_ = wn * 64 + nt_ * 8 + gid; \
        BF[nt_][0] = lds32(bB + SWZ128((uint32_t)(n_ * 128 + k_ * 4))); \
        BF[nt_][1] = lds32(bB + SWZ128((uint32_t)(n_ * 128 + (k_ + 4) * 4))); \
    } \
} while (0)

__global__ __launch_bounds__(512, 1) void mma_gemm_k(
    const float* __restrict__ A, const float* __restrict__ Bt,
    const float* __restrict__ bias, float* __restrict__ C, float* __restrict__ Cs,
    int M, int Ntot, int split, int relu, int roundC)
{
    extern __shared__ __align__(1024) char smem[];
    const uint32_t sb = smem_u32(smem);

    const int tid = threadIdx.x;
    const int lane = tid & 31;
    const int wid = tid >> 5;
    const int gid = lane >> 2;
    const int tig = lane & 3;
    const int wm = wid >> 2;        // 0..3
    const int wn = wid & 3;         // 0..3
    const int m0 = blockIdx.x * 128;
    const int n0 = blockIdx.y * 256;
    const float* BtB = Bt + (size_t)n0 * 256;
    const int nrows = Ntot - n0;

    float acc[2][8][4];
#pragma unroll
    for (int i = 0; i < 2; i++)
#pragma unroll
        for (int j = 0; j < 8; j++)
#pragma unroll
            for (int k = 0; k < 4; k++) acc[i][j][k] = 0.0f;

    const int rA = tid >> 3, cA = tid & 7;   // rA 0..63, cA 0..7

#define LOAD_CHUNK(cc, ss) do { \
    uint32_t aDst = sb + (uint32_t)(ss) * 49152; \
    uint32_t bDst = aDst + 16384; \
    _Pragma("unroll") \
    for (int i_ = 0; i_ < 2; i_++) { \
        int r_ = rA + i_ * 64; \
        int gr_ = m0 + r_; if (gr_ >= M) gr_ = M - 1; \
        cp16(aDst + SWZ128((uint32_t)(r_ * 128 + cA * 16)), \
             (const float4*)A + (size_t)gr_ * 64 + (cc) * 8 + cA); \
    } \
    _Pragma("unroll") \
    for (int i_ = 0; i_ < 4; i_++) { \
        int r_ = rA + i_ * 64; \
        int gr_ = r_; if (gr_ >= nrows) gr_ = nrows - 1; \
        cp16(bDst + SWZ128((uint32_t)(r_ * 128 + cA * 16)), \
             (const float4*)BtB + (size_t)gr_ * 64 + (cc) * 8 + cA); \
    } \
    cp_commit(); \
} while (0)

    LOAD_CHUNK(0, 0);
    LOAD_CHUNK(1, 1);

    int stage = 0;
#pragma unroll 1
    for (int c = 0; c < 8; c++) {
        if (c < 7) cp_wait1(); else cp_wait0();
        __syncthreads();
        if (c + 2 < 8) {
            int s2 = stage + 2; if (s2 >= 3) s2 -= 3;
            LOAD_CHUNK(c + 2, s2);
        }

        const uint32_t aB = sb + (uint32_t)stage * 49152;
        const uint32_t bB = aB + 16384;
#pragma unroll
        for (int ks = 0; ks < 4; ks++) {
            uint32_t af[2][4], bf[8][2];
            LOAD_FRAGS(ks, af, bf);
#pragma unroll
            for (int mt = 0; mt < 2; mt++)
#pragma unroll
                for (int nt = 0; nt < 8; nt++)
                    mma_tf32(acc[mt][nt], af[mt], bf[nt]);
        }
        stage++; if (stage >= 3) stage -= 3;
    }

    // ---- epilogue ----
    const int st2 = Ntot - split;
#pragma unroll
    for (int mt = 0; mt < 2; mt++) {
        int r0 = m0 + wm * 32 + mt * 16 + gid;
        int r1 = r0 + 8;
#pragma unroll
        for (int nt = 0; nt < 8; nt++) {
            int gcol = n0 + wn * 64 + nt * 8 + tig * 2;
            if (gcol >= Ntot) continue;
            float2 b = bias ? *(const float2*)(bias + gcol) : make_float2(0.f, 0.f);
            float2 v0 = make_float2(acc[mt][nt][0] + b.x, acc[mt][nt][1] + b.y);
            float2 v1 = make_float2(acc[mt][nt][2] + b.x, acc[mt][nt][3] + b.y);
            if (relu) {
                v0.x = fmaxf(v0.x, 0.f); v0.y = fmaxf(v0.y, 0.f);
                v1.x = fmaxf(v1.x, 0.f); v1.y = fmaxf(v1.y, 0.f);
            }
            if (roundC) {
                v0.x = rna_tf32(v0.x); v0.y = rna_tf32(v0.y);
                v1.x = rna_tf32(v1.x); v1.y = rna_tf32(v1.y);
            }
            if (gcol < split) {
                if (r0 < M) *(float2*)(C + (size_t)r0 * split + gcol) = v0;
                if (r1 < M) *(float2*)(C + (size_t)r1 * split + gcol) = v1;
            } else {
                int c2 = gcol - split;
                if (r0 < M) *(float2*)(Cs + (size_t)r0 * st2 + c2) = v0;
                if (r1 < M) *(float2*)(Cs + (size_t)r1 * st2 + c2) = v1;
            }
        }
    }
}

// ---------------- GCN aggregation (CSR gather, fused; 2-edge unroll) ----------------
__global__ __launch_bounds__(256) void gcn_agg_k(
    const float* __restrict__ hw, const int* __restrict__ off,
    const int* __restrict__ csrc, const float* __restrict__ coef,
    const float* __restrict__ nrm, const float* __restrict__ bias,
    float* __restrict__ out, float* __restrict__ out_r, float* __restrict__ out2)
{
    int n = blockIdx.x * 8 + (threadIdx.x >> 5);
    int lane = threadIdx.x & 31;
    if (n >= Nn) return;

    float t = nrm[n];
    float nn2 = t * t;
    const float4* self = (const float4*)(hw + (size_t)n * 256) + lane * 2;
    float4 a0 = self[0], a1 = self[1];
    a0.x *= nn2; a0.y *= nn2; a0.z *= nn2; a0.w *= nn2;
    a1.x *= nn2; a1.y *= nn2; a1.z *= nn2; a1.w *= nn2;
    float4 c0 = make_float4(0.f, 0.f, 0.f, 0.f), c1 = c0;

    int p = off[n];
    int p1 = off[n + 1];
    for (; p + 1 < p1; p += 2) {
        int sA_ = csrc[p], sB_ = csrc[p + 1];
        float ca = coef[p], cb = coef[p + 1];
        const float4* ra = (const float4*)(hw + (size_t)sA_ * 256) + lane * 2;
        const float4* rb = (const float4*)(hw + (size_t)sB_ * 256) + lane * 2;
        float4 va0 = ra[0], va1 = ra[1];
        float4 vb0 = rb[0], vb1 = rb[1];
        a0.x = fmaf(va0.x, ca, a0.x); a0.y = fmaf(va0.y, ca, a0.y);
        a0.z = fmaf(va0.z, ca, a0.z); a0.w = fmaf(va0.w, ca, a0.w);
        a1.x = fmaf(va1.x, ca, a1.x); a1.y = fmaf(va1.y, ca, a1.y);
        a1.z = fmaf(va1.z, ca, a1.z); a1.w = fmaf(va1.w, ca, a1.w);
        c0.x = fmaf(vb0.x, cb, c0.x); c0.y = fmaf(vb0.y, cb, c0.y);
        c0.z = fmaf(vb0.z, cb, c0.z); c0.w = fmaf(vb0.w, cb, c0.w);
        c1.x = fmaf(vb1.x, cb, c1.x); c1.y = fmaf(vb1.y, cb, c1.y);
        c1.z = fmaf(vb1.z, cb, c1.z); c1.w = fmaf(vb1.w, cb, c1.w);
    }
    if (p < p1) {
        int s = csrc[p];
        float c = coef[p];
        const float4* r = (const float4*)(hw + (size_t)s * 256) + lane * 2;
        float4 v0 = r[0], v1 = r[1];
        a0.x = fmaf(v0.x, c, a0.x); a0.y = fmaf(v0.y, c, a0.y);
        a0.z = fmaf(v0.z, c, a0.z); a0.w = fmaf(v0.w, c, a0.w);
        a1.x = fmaf(v1.x, c, a1.x); a1.y = fmaf(v1.y, c, a1.y);
        a1.z = fmaf(v1.z, c, a1.z); a1.w = fmaf(v1.w, c, a1.w);
    }
    a0.x += c0.x; a0.y += c0.y; a0.z += c0.z; a0.w += c0.w;
    a1.x += c1.x; a1.y += c1.y; a1.z += c1.z; a1.w += c1.w;

    float4 b0 = ((const float4*)bias)[lane * 2];
    float4 b1 = ((const float4*)bias)[lane * 2 + 1];
    a0.x = fmaxf(a0.x + b0.x, 0.f); a0.y = fmaxf(a0.y + b0.y, 0.f);
    a0.z = fmaxf(a0.z + b0.z, 0.f); a0.w = fmaxf(a0.w + b0.w, 0.f);
    a1.x = fmaxf(a1.x + b1.x, 0.f); a1.y = fmaxf(a1.y + b1.y, 0.f);
    a1.z = fmaxf(a1.z + b1.z, 0.f); a1.w = fmaxf(a1.w + b1.w, 0.f);

    float4* o = (float4*)(out + (size_t)n * 256) + lane * 2;
    o[0] = a0; o[1] = a1;
    float4 r0 = a0, r1 = a1;
    r0.x = rna_tf32(r0.x); r0.y = rna_tf32(r0.y); r0.z = rna_tf32(r0.z); r0.w = rna_tf32(r0.w);
    r1.x = rna_tf32(r1.x); r1.y = rna_tf32(r1.y); r1.z = rna_tf32(r1.z); r1.w = rna_tf32(r1.w);
    float4* orr = (float4*)(out_r + (size_t)n * 256) + lane * 2;
    orr[0] = r0; orr[1] = r1;
    if (out2) {
        float4* o2 = (float4*)(out2 + (size_t)n * 256) + lane * 2;
        o2[0] = a0; o2[1] = a1;
    }
}

// ---------------- edge MLP over CSR order ----------------
__global__ __launch_bounds__(256) void edge_mlp_csr_k(
    const float* __restrict__ AB, const int* __restrict__ off,
    const int* __restrict__ csrc, const int* __restrict__ eid,
    const float* __restrict__ Wh2, const float* __restrict__ bh2,
    float* __restrict__ hier)
{
    int d = blockIdx.x * 8 + (threadIdx.x >> 5);
    int lane = threadIdx.x & 31;
    if (d >= Nn) return;

    float w[8][3];
#pragma unroll
    for (int i = 0; i < 8; i++) {
        int f = lane * 8 + i;
        w[i][0] = Wh2[f * 3 + 0];
        w[i][1] = Wh2[f * 3 + 1];
        w[i][2] = Wh2[f * 3 + 2];
    }
    float bb0 = bh2[0], bb1 = bh2[1], bb2 = bh2[2];

    const float4* bp = (const float4*)(AB + (size_t)d * 512 + 256) + lane * 2;
    float4 B0 = bp[0], B1 = bp[1];

    int p1 = off[d + 1];
    for (int p = off[d]; p < p1; p++) {
        int s = csrc[p];
        int e = eid[p];
        const float4* ap = (const float4*)(AB + (size_t)s * 512) + lane * 2;
        float4 A0 = ap[0], A1 = ap[1];
        float s0 = 0.f, s1 = 0.f, s2 = 0.f, t;
        t = fmaxf(A0.x + B0.x, 0.f); s0 = fmaf(t, w[0][0], s0); s1 = fmaf(t, w[0][1], s1); s2 = fmaf(t, w[0][2], s2);
        t = fmaxf(A0.y + B0.y, 0.f); s0 = fmaf(t, w[1][0], s0); s1 = fmaf(t, w[1][1], s1); s2 = fmaf(t, w[1][2], s2);
        t = fmaxf(A0.z + B0.z, 0.f); s0 = fmaf(t, w[2][0], s0); s1 = fmaf(t, w[2][1], s1); s2 = fmaf(t, w[2][2], s2);
        t = fmaxf(A0.w + B0.w, 0.f); s0 = fmaf(t, w[3][0], s0); s1 = fmaf(t, w[3][1], s1); s2 = fmaf(t, w[3][2], s2);
        t = fmaxf(A1.x + B1.x, 0.f); s0 = fmaf(t, w[4][0], s0); s1 = fmaf(t, w[4][1], s1); s2 = fmaf(t, w[4][2], s2);
        t = fmaxf(A1.y + B1.y, 0.f); s0 = fmaf(t, w[5][0], s0); s1 = fmaf(t, w[5][1], s1); s2 = fmaf(t, w[5][2], s2);
        t = fmaxf(A1.z + B1.z, 0.f); s0 = fmaf(t, w[6][0], s0); s1 = fmaf(t, w[6][1], s1); s2 = fmaf(t, w[6][2], s2);
        t = fmaxf(A1.w + B1.w, 0.f); s0 = fmaf(t, w[7][0], s0); s1 = fmaf(t, w[7][1], s1); s2 = fmaf(t, w[7][2], s2);
#pragma unroll
        for (int o = 16; o; o >>= 1) {
            s0 += __shfl_down_sync(0xffffffffu, s0, o);
            s1 += __shfl_down_sync(0xffffffffu, s1, o);
            s2 += __shfl_down_sync(0xffffffffu, s2, o);
        }
        if (lane == 0) {
            hier[(size_t)e * 3 + 0] = s0 + bb0;
            hier[(size_t)e * 3 + 1] = s1 + bb1;
            hier[(size_t)e * 3 + 2] = s2 + bb2;
        }
    }
}

// ---------------- perm head (relu applied here) ----------------
__global__ __launch_bounds__(256) void perm_k(
    const float* __restrict__ ph, const float* __restrict__ Wp2,
    const float* __restrict__ bp2, float* __restrict__ perm)
{
    int n = blockIdx.x * 8 + (threadIdx.x >> 5);
    int lane = threadIdx.x & 31;
    if (n >= Nn) return;
    float4 p = ((const float4*)ph)[(size_t)n * 32 + lane];
    p.x = fmaxf(p.x, 0.f); p.y = fmaxf(p.y, 0.f);
    p.z = fmaxf(p.z, 0.f); p.w = fmaxf(p.w, 0.f);
    float4 w = ((const float4*)Wp2)[lane];
    float s = p.x * w.x + p.y * w.y + p.z * w.z + p.w * w.w;
#pragma unroll
    for (int o = 16; o; o >>= 1) s += __shfl_down_sync(0xffffffffu, s, o);
    if (lane == 0) perm[n] = 1.0f / (1.0f + expf(-(s + bp2[0])));
}

// ---------------- launch ----------------
extern "C" void kernel_launch(void* const* d_in, const int* in_sizes, int n_in,
                              void* d_out, int out_size) {
    const float* x    = (const float*)d_in[0];
    const int*   ei   = (const int*)d_in[1];
    const float* W_in = (const float*)d_in[2];
    const float* b_in = (const float*)d_in[3];
    const float* Wg   = (const float*)d_in[4];
    const float* bg   = (const float*)d_in[5];
    const float* Wh1  = (const float*)d_in[6];
    const float* bh1  = (const float*)d_in[7];
    const float* Wh2  = (const float*)d_in[8];
    const float* bh2  = (const float*)d_in[9];
    const float* Wp1  = (const float*)d_in[10];
    const float* bp1  = (const float*)d_in[11];
    const float* Wp2  = (const float*)d_in[12];
    const float* bp2  = (const float*)d_in[13];

    const int* src = ei;
    const int* dst = ei + Ee;

    float *hr, *hw, *AB, *ph, *nrm, *wt, *b640, *coef;
    int *deg, *off, *cur, *csrc, *eid;
    cudaGetSymbolAddress((void**)&hr,   g_hr);
    cudaGetSymbolAddress((void**)&hw,   g_hw);
    cudaGetSymbolAddress((void**)&AB,   g_AB);
    cudaGetSymbolAddress((void**)&ph,   g_ph);
    cudaGetSymbolAddress((void**)&nrm,  g_norm);
    cudaGetSymbolAddress((void**)&wt,   g_wt);
    cudaGetSymbolAddress((void**)&b640, g_b640);
    cudaGetSymbolAddress((void**)&deg,  g_deg);
    cudaGetSymbolAddress((void**)&off,  g_off);
    cudaGetSymbolAddress((void**)&cur,  g_cur);
    cudaGetSymbolAddress((void**)&csrc, g_csrc);
    cudaGetSymbolAddress((void**)&eid,  g_eid);
    cudaGetSymbolAddress((void**)&coef, g_coef);

    float* out_h     = (float*)d_out;
    float* out_hier  = out_h + (size_t)Nn * Hh;
    float* out_perm  = out_hier + (size_t)Ee * 3;
    float* out_inter = out_perm + Nn;

    cudaFuncSetAttribute(mma_gemm_k, cudaFuncAttributeMaxDynamicSharedMemorySize, 147456);
    const int SM = 147456;   // 3 stages x (16KB A + 32KB B)

    float* wt_in = wt;
    float* wt_g  = wt + 65536;
    float* wt_hp = wt + 65536 * 4;   // [Wh1_top|Wh1_bot|Wp1] = 640 rows x 256

    const int mtiles = (Nn + 127) / 128;
    const int nblocks = (Nn + 7) / 8;

    // setup (launches 1..3)
    pack_all_k<<<(65536 * 6 + 32768 + 255) / 256, 256>>>(W_in, Wg, Wh1, Wp1, wt);
    bias640_k<<<3, 256>>>(bh1, bp1, b640);
    round_x_k<<<(Nn * 64 + 255) / 256, 256>>>(x, AB);

    // launch 4: input GEMM (profiler samples this) -> hr (rounded, internal only)
    mma_gemm_k<<<dim3(mtiles, 1), 512, SM>>>(AB, wt_in, b_in, hr, nullptr, Nn, 256, 256, 1, 1);

    // CSR build
    deg_zero_k<<<(Nn + 255) / 256, 256>>>(deg);
    deg_hist_k<<<(Ee + 255) / 256, 256>>>(dst, deg);
    scan_k<<<1, 1024>>>(deg, off, cur, nrm);
    fill_k<<<(Ee + 255) / 256, 256>>>(src, dst, nrm, cur, csrc, eid, coef);

    // 3 GCN layers: GEMM(hr -> hw), agg(hw -> lout exact, hr rounded)
    for (int l = 0; l < 3; l++) {
        mma_gemm_k<<<dim3(mtiles, 1), 512, SM>>>(
            hr, wt_g + (size_t)l * 65536, nullptr, hw, nullptr, Nn, 256, 256, 0, 0);
        float* lout = out_inter + (size_t)l * Nn * Hh;
        float* lout2 = (l == 2) ? out_h : nullptr;
        gcn_agg_k<<<nblocks, 256>>>(hw, off, csrc, coef, nrm, bg + (size_t)l * Hh,
                                    lout, hr, lout2);
    }

    // fused edge-MLP + perm-hidden GEMM: N=640 -> AB (cols 0..511), ph (512..639)
    mma_gemm_k<<<dim3(mtiles, 3), 512, SM>>>(hr, wt_hp, b640, AB, ph, Nn, 640, 512, 0, 0);
    edge_mlp_csr_k<<<nblocks, 256>>>(AB, off, csrc, eid, Wh2, bh2, out_hier);
    perm_k<<<nblocks, 256>>>(ph, Wp2, bp2, out_perm);
}

// round 8
// speedup vs baseline: 1.0151x; 1.0151x over previous
#include <cuda_runtime.h>
#include <cstdint>
#include <math.h>

#define Nn  50000
#define FIN 256
#define Hh  256
#define Ee  400000

// ---------------- scratch (static device globals; no allocation) ----------------
__device__ float g_hr[(size_t)Nn * Hh];     // tf32-pre-rounded GEMM input (rotated+paired layout)
__device__ float g_hw[(size_t)Nn * Hh];
__device__ float g_AB[(size_t)Nn * 512];    // xr (rotated layout) first, then edge-MLP pre-acts (logical)
__device__ float g_ph[(size_t)Nn * (Hh / 2)];
__device__ float g_norm[Nn];
__device__ float g_wt[65536 * 6 + 32768];   // packed/transposed tf32 weights (rotated+paired layout)
__device__ float g_b640[640];
// CSR (by dst)
__device__ int   g_deg[Nn];
__device__ int   g_off[Nn + 1];
__device__ int   g_cur[Nn];
__device__ int   g_csrc[Ee];
__device__ int   g_eid[Ee];
__device__ float g_coef[Ee];

// Layout of every GEMM operand row (256 floats), designed for conflict-free v2 LDS:
//   logical k -> position  (c = k>>5 chunk, ks = (k>>3)&3, t = k&3, j = (k&7)>>2)
//   pos = c*32 + ((ks + row) & 3)*8 + 2*t + j
// i.e. per 32-chunk: 4 segments of 8, segment rotated by row&3, K-pairs (k, k+4) adjacent.

// ---------------- PTX helpers (baseline sm_100, no 'a' features) ----------------
__device__ __forceinline__ uint32_t smem_u32(const void* p) {
    uint32_t a;
    asm("{ .reg .u64 t; cvta.to.shared.u64 t, %1; cvt.u32.u64 %0, t; }" : "=r"(a) : "l"(p));
    return a;
}
__device__ __forceinline__ float rna_tf32(float v) {
    uint32_t u;
    asm("cvt.rna.tf32.f32 %0, %1;" : "=r"(u) : "f"(v));
    return __uint_as_float(u);
}
__device__ __forceinline__ void lds64(uint32_t& a, uint32_t& b, uint32_t addr) {
    asm volatile("ld.shared.v2.u32 {%0,%1}, [%2];" : "=r"(a), "=r"(b) : "r"(addr));
}
__device__ __forceinline__ void cp16(uint32_t dst, const void* src) {
    asm volatile("cp.async.cg.shared.global [%0], [%1], 16;" :: "r"(dst), "l"(src) : "memory");
}
__device__ __forceinline__ void cp_commit() {
    asm volatile("cp.async.commit_group;" ::: "memory");
}
__device__ __forceinline__ void cp_wait0() {
    asm volatile("cp.async.wait_group 0;" ::: "memory");
}
__device__ __forceinline__ void cp_wait1() {
    asm volatile("cp.async.wait_group 1;" ::: "memory");
}
__device__ __forceinline__ void mma_tf32(float* c, const uint32_t* a, const uint32_t* b) {
    asm volatile(
        "mma.sync.aligned.m16n8k8.row.col.f32.tf32.tf32.f32 "
        "{%0,%1,%2,%3},{%4,%5,%6,%7},{%8,%9},{%0,%1,%2,%3};"
        : "+f"(c[0]), "+f"(c[1]), "+f"(c[2]), "+f"(c[3])
        : "r"(a[0]), "r"(a[1]), "r"(a[2]), "r"(a[3]), "r"(b[0]), "r"(b[1]));
}

// position of logical column f in a rotated row (float units)
__device__ __forceinline__ int rot_pos(int f, int row) {
    int seg = (((f >> 3) & 3) + row) & 3;
    return (f & ~31) + seg * 8 + ((f & 3) << 1) + ((f & 7) >> 2);
}

// ---------------- one-shot weight pack (transpose + tf32 round + rotated layout) ----------------
__global__ void pack_all_k(const float* __restrict__ W_in, const float* __restrict__ Wg,
                           const float* __restrict__ Wh1, const float* __restrict__ Wp1,
                           float* __restrict__ wt) {
    int i = blockIdx.x * blockDim.x + threadIdx.x;
    const int T = 65536 * 6 + 32768;
    if (i >= T) return;
    int nrow = i >> 8;           // row in wt (all regions 256-row aligned -> mod-4 consistent)
    int pos = i & 255;           // storage position within row
    // invert layout: pos -> logical k
    int c = pos >> 5;
    int wpos = pos & 31;
    int seg = wpos >> 3;
    int q = wpos & 7;
    int ks = (seg - nrow) & 3;
    int k = (c << 5) + (ks << 3) + (q >> 1) + ((q & 1) << 2);

    float v;
    if (i < 65536) {
        v = W_in[(size_t)k * 256 + nrow];
    } else if (i < 4 * 65536) {
        int j = i - 65536;
        int l = j >> 16;
        int n = (j >> 8) & 255;
        v = Wg[(size_t)l * 65536 + (size_t)k * 256 + n];
    } else if (i < 6 * 65536) {
        int j = i - 4 * 65536;
        int half = j >> 16;
        int n = (j >> 8) & 255;
        v = Wh1[(size_t)(half * 256 + k) * 256 + n];
    } else {
        int j = i - 6 * 65536;
        int n = j >> 8;           // 0..127
        v = Wp1[(size_t)k * 128 + n];
    }
    wt[i] = rna_tf32(v);
}
__global__ void bias640_k(const float* __restrict__ bh1, const float* __restrict__ bp1,
                          float* __restrict__ b640) {
    int i = blockIdx.x * blockDim.x + threadIdx.x;
    if (i >= 640) return;
    b640[i] = (i < 256) ? bh1[i] : (i < 512 ? 0.0f : bp1[i - 512]);
}
// pre-round x to tf32 and store in rotated+paired layout
__global__ void round_x_k(const float* __restrict__ x, float* __restrict__ xr) {
    int i = blockIdx.x * blockDim.x + threadIdx.x;
    if (i >= Nn * 32) return;
    int n = i >> 5, g8 = i & 31;          // 8-feature group
    int c = g8 >> 2, ks = g8 & 3;
    float4 v0 = ((const float4*)x)[(size_t)n * 64 + g8 * 2];
    float4 v1 = ((const float4*)x)[(size_t)n * 64 + g8 * 2 + 1];
    v0.x = rna_tf32(v0.x); v0.y = rna_tf32(v0.y); v0.z = rna_tf32(v0.z); v0.w = rna_tf32(v0.w);
    v1.x = rna_tf32(v1.x); v1.y = rna_tf32(v1.y); v1.z = rna_tf32(v1.z); v1.w = rna_tf32(v1.w);
    int seg = (ks + n) & 3;
    float4* dst = (float4*)(xr + (size_t)n * 256 + c * 32 + seg * 8);
    dst[0] = make_float4(v0.x, v1.x, v0.y, v1.y);
    dst[1] = make_float4(v0.z, v1.z, v0.w, v1.w);
}

// ---------------- CSR build ----------------
__global__ void deg_zero_k(int* deg) {
    int i = blockIdx.x * blockDim.x + threadIdx.x;
    if (i < Nn) deg[i] = 0;
}
__global__ void deg_hist_k(const int* __restrict__ dst, int* deg) {
    int e = blockIdx.x * blockDim.x + threadIdx.x;
    if (e < Ee) atomicAdd(&deg[dst[e]], 1);
}
__global__ __launch_bounds__(1024) void scan_k(const int* __restrict__ deg,
                                               int* __restrict__ off, int* __restrict__ cur,
                                               float* __restrict__ nrm) {
    __shared__ int part[1024];
    const int CH = (Nn + 1023) / 1024;
    int t = threadIdx.x;
    int start = t * CH;
    int end = start + CH; if (end > Nn) end = Nn;
    int s = 0;
    for (int i = start; i < end; i++) s += deg[i];
    part[t] = s;
    __syncthreads();
    for (int o = 1; o < 1024; o <<= 1) {
        int v = (t >= o) ? part[t - o] : 0;
        __syncthreads();
        part[t] += v;
        __syncthreads();
    }
    int run = (t > 0) ? part[t - 1] : 0;
    for (int i = start; i < end; i++) {
        int d = deg[i];
        off[i] = run; cur[i] = run;
        nrm[i] = rsqrtf((float)d + 1.0f);
        run += d;
    }
    if (t == 1023) off[Nn] = run;
}
__global__ void fill_k(const int* __restrict__ src, const int* __restrict__ dst,
                       const float* __restrict__ nrm, int* cur,
                       int* __restrict__ csrc, int* __restrict__ eid,
                       float* __restrict__ coef) {
    int e = blockIdx.x * blockDim.x + threadIdx.x;
    if (e >= Ee) return;
    int s = src[e], d = dst[e];
    int pos = atomicAdd(&cur[d], 1);
    csrc[pos] = s;
    eid[pos] = e;
    coef[pos] = nrm[s] * nrm[d];
}

// ---------------- TF32 mma.sync GEMM, CTA 128x256, 512 threads, rotated layout ----------------
// A & Bt stored in rotated+paired layout; cp.async is an identity copy; all SMEM
// reads are ld.shared.v2 with [base[ks] + compile-time-imm] addressing (no per-load ALU).
__global__ __launch_bounds__(512, 1) void mma_gemm_k(
    const float* __restrict__ A, const float* __restrict__ Bt,
    const float* __restrict__ bias, float* __restrict__ C, float* __restrict__ Cs,
    int M, int Ntot, int split, int relu, int roundC)
{
    extern __shared__ __align__(1024) char smem[];
    const uint32_t sb = smem_u32(smem);

    const int tid = threadIdx.x;
    const int lane = tid & 31;
    const int wid = tid >> 5;
    const int gid = lane >> 2;      // 0..7
    const int tig = lane & 3;       // 0..3
    const int wm = wid >> 2;        // 0..3
    const int wn = wid & 3;         // 0..3
    const int m0 = blockIdx.x * 128;
    const int n0 = blockIdx.y * 256;
    const float* BtB = Bt + (size_t)n0 * 256;
    const int nrows = Ntot - n0;

    float acc[2][8][4];
#pragma unroll
    for (int i = 0; i < 2; i++)
#pragma unroll
        for (int j = 0; j < 8; j++)
#pragma unroll
            for (int k = 0; k < 4; k++) acc[i][j][k] = 0.0f;

    const int rA = tid >> 3, cA = tid & 7;

    // stage-invariant read-offset components
    uint32_t colk[4];
#pragma unroll
    for (int ks = 0; ks < 4; ks++)
        colk[ks] = 32u * (uint32_t)((ks + gid) & 3) + 8u * (uint32_t)tig;
    const uint32_t aRow = (uint32_t)(wm * 32 + gid) * 128u;
    const uint32_t bRow = (uint32_t)(wn * 64 + gid) * 128u;

#define LOAD_CHUNK(cc, ss) do { \
    uint32_t aDst = sb + (uint32_t)(ss) * 49152 + (uint32_t)rA * 128 + (uint32_t)cA * 16; \
    uint32_t bDst = aDst + 16384; \
    _Pragma("unroll") \
    for (int i_ = 0; i_ < 2; i_++) { \
        int r_ = rA + i_ * 64; \
        int gr_ = m0 + r_; if (gr_ >= M) gr_ = M - 1; \
        cp16(aDst + (uint32_t)i_ * 8192, \
             (const float4*)A + (size_t)gr_ * 64 + (cc) * 8 + cA); \
    } \
    _Pragma("unroll") \
    for (int i_ = 0; i_ < 4; i_++) { \
        int r_ = rA + i_ * 64; \
        int gr_ = r_; if (gr_ >= nrows) gr_ = nrows - 1; \
        cp16(bDst + (uint32_t)i_ * 8192, \
             (const float4*)BtB + (size_t)gr_ * 64 + (cc) * 8 + cA); \
    } \
    cp_commit(); \
} while (0)

    LOAD_CHUNK(0, 0);
    LOAD_CHUNK(1, 1);

    int stage = 0;
#pragma unroll 1
    for (int c = 0; c < 8; c++) {
        if (c < 7) cp_wait1(); else cp_wait0();
        __syncthreads();
        if (c + 2 < 8) {
            int s2 = stage + 2; if (s2 >= 3) s2 -= 3;
            LOAD_CHUNK(c + 2, s2);
        }

        const uint32_t aT = sb + (uint32_t)stage * 49152 + aRow;
        const uint32_t bT = sb + (uint32_t)stage * 49152 + 16384 + bRow;
#pragma unroll
        for (int ks = 0; ks < 4; ks++) {
            const uint32_t baseA = aT + colk[ks];
            const uint32_t baseB = bT + colk[ks];
            uint32_t af[2][4], bf[8][2];
            lds64(af[0][0], af[0][2], baseA);
            lds64(af[0][1], af[0][3], baseA + 1024);
            lds64(af[1][0], af[1][2], baseA + 2048);
            lds64(af[1][1], af[1][3], baseA + 3072);
#pragma unroll
            for (int nt = 0; nt < 8; nt++)
                lds64(bf[nt][0], bf[nt][1], baseB + (uint32_t)nt * 1024);
#pragma unroll
            for (int mt = 0; mt < 2; mt++)
#pragma unroll
                for (int nt = 0; nt < 8; nt++)
                    mma_tf32(acc[mt][nt], af[mt], bf[nt]);
        }
        stage++; if (stage >= 3) stage -= 3;
    }

    // ---- epilogue ----
    const int st2 = Ntot - split;
#pragma unroll
    for (int mt = 0; mt < 2; mt++) {
        int r0 = m0 + wm * 32 + mt * 16 + gid;
        int r1 = r0 + 8;
#pragma unroll
        for (int nt = 0; nt < 8; nt++) {
            int gcol = n0 + wn * 64 + nt * 8 + tig * 2;
            if (gcol >= Ntot) continue;
            float2 b = bias ? *(const float2*)(bias + gcol) : make_float2(0.f, 0.f);
            float2 v0 = make_float2(acc[mt][nt][0] + b.x, acc[mt][nt][1] + b.y);
            float2 v1 = make_float2(acc[mt][nt][2] + b.x, acc[mt][nt][3] + b.y);
            if (relu) {
                v0.x = fmaxf(v0.x, 0.f); v0.y = fmaxf(v0.y, 0.f);
                v1.x = fmaxf(v1.x, 0.f); v1.y = fmaxf(v1.y, 0.f);
            }
            if (roundC) {
                // rounded + rotated-layout scalar stores (hr); split == Ntot here
                v0.x = rna_tf32(v0.x); v0.y = rna_tf32(v0.y);
                v1.x = rna_tf32(v1.x); v1.y = rna_tf32(v1.y);
                if (r0 < M) {
                    C[(size_t)r0 * split + rot_pos(gcol, r0)]     = v0.x;
                    C[(size_t)r0 * split + rot_pos(gcol + 1, r0)] = v0.y;
                }
                if (r1 < M) {
                    C[(size_t)r1 * split + rot_pos(gcol, r1)]     = v1.x;
                    C[(size_t)r1 * split + rot_pos(gcol + 1, r1)] = v1.y;
                }
            } else if (gcol < split) {
                if (r0 < M) *(float2*)(C + (size_t)r0 * split + gcol) = v0;
                if (r1 < M) *(float2*)(C + (size_t)r1 * split + gcol) = v1;
            } else {
                int c2 = gcol - split;
                if (r0 < M) *(float2*)(Cs + (size_t)r0 * st2 + c2) = v0;
                if (r1 < M) *(float2*)(Cs + (size_t)r1 * st2 + c2) = v1;
            }
        }
    }
}

// ---------------- GCN aggregation (CSR gather; hr written in rotated layout) ----------------
__global__ __launch_bounds__(256) void gcn_agg_k(
    const float* __restrict__ hw, const int* __restrict__ off,
    const int* __restrict__ csrc, const float* __restrict__ coef,
    const float* __restrict__ nrm, const float* __restrict__ bias,
    float* __restrict__ out, float* __restrict__ out_r, float* __restrict__ out2)
{
    int n = blockIdx.x * 8 + (threadIdx.x >> 5);
    int lane = threadIdx.x & 31;
    if (n >= Nn) return;

    float t = nrm[n];
    float nn2 = t * t;
    const float4* self = (const float4*)(hw + (size_t)n * 256) + lane * 2;
    float4 a0 = self[0], a1 = self[1];
    a0.x *= nn2; a0.y *= nn2; a0.z *= nn2; a0.w *= nn2;
    a1.x *= nn2; a1.y *= nn2; a1.z *= nn2; a1.w *= nn2;
    float4 c0 = make_float4(0.f, 0.f, 0.f, 0.f), c1 = c0;

    int p = off[n];
    int p1 = off[n + 1];
    for (; p + 1 < p1; p += 2) {
        int sA_ = csrc[p], sB_ = csrc[p + 1];
        float ca = coef[p], cb = coef[p + 1];
        const float4* ra = (const float4*)(hw + (size_t)sA_ * 256) + lane * 2;
        const float4* rb = (const float4*)(hw + (size_t)sB_ * 256) + lane * 2;
        float4 va0 = ra[0], va1 = ra[1];
        float4 vb0 = rb[0], vb1 = rb[1];
        a0.x = fmaf(va0.x, ca, a0.x); a0.y = fmaf(va0.y, ca, a0.y);
        a0.z = fmaf(va0.z, ca, a0.z); a0.w = fmaf(va0.w, ca, a0.w);
        a1.x = fmaf(va1.x, ca, a1.x); a1.y = fmaf(va1.y, ca, a1.y);
        a1.z = fmaf(va1.z, ca, a1.z); a1.w = fmaf(va1.w, ca, a1.w);
        c0.x = fmaf(vb0.x, cb, c0.x); c0.y = fmaf(vb0.y, cb, c0.y);
        c0.z = fmaf(vb0.z, cb, c0.z); c0.w = fmaf(vb0.w, cb, c0.w);
        c1.x = fmaf(vb1.x, cb, c1.x); c1.y = fmaf(vb1.y, cb, c1.y);
        c1.z = fmaf(vb1.z, cb, c1.z); c1.w = fmaf(vb1.w, cb, c1.w);
    }
    if (p < p1) {
        int s = csrc[p];
        float c = coef[p];
        const float4* r = (const float4*)(hw + (size_t)s * 256) + lane * 2;
        float4 v0 = r[0], v1 = r[1];
        a0.x = fmaf(v0.x, c, a0.x); a0.y = fmaf(v0.y, c, a0.y);
        a0.z = fmaf(v0.z, c, a0.z); a0.w = fmaf(v0.w, c, a0.w);
        a1.x = fmaf(v1.x, c, a1.x); a1.y = fmaf(v1.y, c, a1.y);
        a1.z = fmaf(v1.z, c, a1.z); a1.w = fmaf(v1.w, c, a1.w);
    }
    a0.x += c0.x; a0.y += c0.y; a0.z += c0.z; a0.w += c0.w;
    a1.x += c1.x; a1.y += c1.y; a1.z += c1.z; a1.w += c1.w;

    float4 b0 = ((const float4*)bias)[lane * 2];
    float4 b1 = ((const float4*)bias)[lane * 2 + 1];
    a0.x = fmaxf(a0.x + b0.x, 0.f); a0.y = fmaxf(a0.y + b0.y, 0.f);
    a0.z = fmaxf(a0.z + b0.z, 0.f); a0.w = fmaxf(a0.w + b0.w, 0.f);
    a1.x = fmaxf(a1.x + b1.x, 0.f); a1.y = fmaxf(a1.y + b1.y, 0.f);
    a1.z = fmaxf(a1.z + b1.z, 0.f); a1.w = fmaxf(a1.w + b1.w, 0.f);

    float4* o = (float4*)(out + (size_t)n * 256) + lane * 2;
    o[0] = a0; o[1] = a1;

    // rotated+paired rounded copy for the next GEMM: lane holds features lane*8..+7
    {
        int cc = lane >> 2, ks = lane & 3;
        int seg = (ks + n) & 3;
        float4* dst = (float4*)(out_r + (size_t)n * 256 + cc * 32 + seg * 8);
        dst[0] = make_float4(rna_tf32(a0.x), rna_tf32(a1.x), rna_tf32(a0.y), rna_tf32(a1.y));
        dst[1] = make_float4(rna_tf32(a0.z), rna_tf32(a1.z), rna_tf32(a0.w), rna_tf32(a1.w));
    }
    if (out2) {
        float4* o2 = (float4*)(out2 + (size_t)n * 256) + lane * 2;
        o2[0] = a0; o2[1] = a1;
    }
}

// ---------------- edge MLP over CSR order ----------------
__global__ __launch_bounds__(256) void edge_mlp_csr_k(
    const float* __restrict__ AB, const int* __restrict__ off,
    const int* __restrict__ csrc, const int* __restrict__ eid,
    const float* __restrict__ Wh2, const float* __restrict__ bh2,
    float* __restrict__ hier)
{
    int d = blockIdx.x * 8 + (threadIdx.x >> 5);
    int lane = threadIdx.x & 31;
    if (d >= Nn) return;

    float w[8][3];
#pragma unroll
    for (int i = 0; i < 8; i++) {
        int f = lane * 8 + i;
        w[i][0] = Wh2[f * 3 + 0];
        w[i][1] = Wh2[f * 3 + 1];
        w[i][2] = Wh2[f * 3 + 2];
    }
    float bb0 = bh2[0], bb1 = bh2[1], bb2 = bh2[2];

    const float4* bp = (const float4*)(AB + (size_t)d * 512 + 256) + lane * 2;
    float4 B0 = bp[0], B1 = bp[1];

    int p1 = off[d + 1];
    for (int p = off[d]; p < p1; p++) {
        int s = csrc[p];
        int e = eid[p];
        const float4* ap = (const float4*)(AB + (size_t)s * 512) + lane * 2;
        float4 A0 = ap[0], A1 = ap[1];
        float s0 = 0.f, s1 = 0.f, s2 = 0.f, t;
        t = fmaxf(A0.x + B0.x, 0.f); s0 = fmaf(t, w[0][0], s0); s1 = fmaf(t, w[0][1], s1); s2 = fmaf(t, w[0][2], s2);
        t = fmaxf(A0.y + B0.y, 0.f); s0 = fmaf(t, w[1][0], s0); s1 = fmaf(t, w[1][1], s1); s2 = fmaf(t, w[1][2], s2);
        t = fmaxf(A0.z + B0.z, 0.f); s0 = fmaf(t, w[2][0], s0); s1 = fmaf(t, w[2][1], s1); s2 = fmaf(t, w[2][2], s2);
        t = fmaxf(A0.w + B0.w, 0.f); s0 = fmaf(t, w[3][0], s0); s1 = fmaf(t, w[3][1], s1); s2 = fmaf(t, w[3][2], s2);
        t = fmaxf(A1.x + B1.x, 0.f); s0 = fmaf(t, w[4][0], s0); s1 = fmaf(t, w[4][1], s1); s2 = fmaf(t, w[4][2], s2);
        t = fmaxf(A1.y + B1.y, 0.f); s0 = fmaf(t, w[5][0], s0); s1 = fmaf(t, w[5][1], s1); s2 = fmaf(t, w[5][2], s2);
        t = fmaxf(A1.z + B1.z, 0.f); s0 = fmaf(t, w[6][0], s0); s1 = fmaf(t, w[6][1], s1); s2 = fmaf(t, w[6][2], s2);
        t = fmaxf(A1.w + B1.w, 0.f); s0 = fmaf(t, w[7][0], s0); s1 = fmaf(t, w[7][1], s1); s2 = fmaf(t, w[7][2], s2);
#pragma unroll
        for (int o = 16; o; o >>= 1) {
            s0 += __shfl_down_sync(0xffffffffu, s0, o);
            s1 += __shfl_down_sync(0xffffffffu, s1, o);
            s2 += __shfl_down_sync(0xffffffffu, s2, o);
        }
        if (lane == 0) {
            hier[(size_t)e * 3 + 0] = s0 + bb0;
            hier[(size_t)e * 3 + 1] = s1 + bb1;
            hier[(size_t)e * 3 + 2] = s2 + bb2;
        }
    }
}

// ---------------- perm head (relu applied here) ----------------
__global__ __launch_bounds__(256) void perm_k(
    const float* __restrict__ ph, const float* __restrict__ Wp2,
    const float* __restrict__ bp2, float* __restrict__ perm)
{
    int n = blockIdx.x * 8 + (threadIdx.x >> 5);
    int lane = threadIdx.x & 31;
    if (n >= Nn) return;
    float4 p = ((const float4*)ph)[(size_t)n * 32 + lane];
    p.x = fmaxf(p.x, 0.f); p.y = fmaxf(p.y, 0.f);
    p.z = fmaxf(p.z, 0.f); p.w = fmaxf(p.w, 0.f);
    float4 w = ((const float4*)Wp2)[lane];
    float s = p.x * w.x + p.y * w.y + p.z * w.z + p.w * w.w;
#pragma unroll
    for (int o = 16; o; o >>= 1) s += __shfl_down_sync(0xffffffffu, s, o);
    if (lane == 0) perm[n] = 1.0f / (1.0f + expf(-(s + bp2[0])));
}

// ---------------- launch ----------------
extern "C" void kernel_launch(void* const* d_in, const int* in_sizes, int n_in,
                              void* d_out, int out_size) {
    const float* x    = (const float*)d_in[0];
    const int*   ei   = (const int*)d_in[1];
    const float* W_in = (const float*)d_in[2];
    const float* b_in = (const float*)d_in[3];
    const float* Wg   = (const float*)d_in[4];
    const float* bg   = (const float*)d_in[5];
    const float* Wh1  = (const float*)d_in[6];
    const float* bh1  = (const float*)d_in[7];
    const float* Wh2  = (const float*)d_in[8];
    const float* bh2  = (const float*)d_in[9];
    const float* Wp1  = (const float*)d_in[10];
    const float* bp1  = (const float*)d_in[11];
    const float* Wp2  = (const float*)d_in[12];
    const float* bp2  = (const float*)d_in[13];

    const int* src = ei;
    const int* dst = ei + Ee;

    float *hr, *hw, *AB, *ph, *nrm, *wt, *b640, *coef;
    int *deg, *off, *cur, *csrc, *eid;
    cudaGetSymbolAddress((void**)&hr,   g_hr);
    cudaGetSymbolAddress((void**)&hw,   g_hw);
    cudaGetSymbolAddress((void**)&AB,   g_AB);
    cudaGetSymbolAddress((void**)&ph,   g_ph);
    cudaGetSymbolAddress((void**)&nrm,  g_norm);
    cudaGetSymbolAddress((void**)&wt,   g_wt);
    cudaGetSymbolAddress((void**)&b640, g_b640);
    cudaGetSymbolAddress((void**)&deg,  g_deg);
    cudaGetSymbolAddress((void**)&off,  g_off);
    cudaGetSymbolAddress((void**)&cur,  g_cur);
    cudaGetSymbolAddress((void**)&csrc, g_csrc);
    cudaGetSymbolAddress((void**)&eid,  g_eid);
    cudaGetSymbolAddress((void**)&coef, g_coef);

    float* out_h     = (float*)d_out;
    float* out_hier  = out_h + (size_t)Nn * Hh;
    float* out_perm  = out_hier + (size_t)Ee * 3;
    float* out_inter = out_perm + Nn;

    cudaFuncSetAttribute(mma_gemm_k, cudaFuncAttributeMaxDynamicSharedMemorySize, 147456);
    const int SM = 147456;   // 3 stages x (16KB A + 32KB B)

    float* wt_in = wt;
    float* wt_g  = wt + 65536;
    float* wt_hp = wt + 65536 * 4;   // [Wh1_top|Wh1_bot|Wp1] = 640 rows x 256

    const int mtiles = (Nn + 127) / 128;
    const int nblocks = (Nn + 7) / 8;

    // setup
    pack_all_k<<<(65536 * 6 + 32768 + 255) / 256, 256>>>(W_in, Wg, Wh1, Wp1, wt);
    bias640_k<<<3, 256>>>(bh1, bp1, b640);
    round_x_k<<<(Nn * 32 + 255) / 256, 256>>>(x, AB);

    // launch 4: input GEMM (profiler samples this) -> hr (rounded+rotated, internal only)
    mma_gemm_k<<<dim3(mtiles, 1), 512, SM>>>(AB, wt_in, b_in, hr, nullptr, Nn, 256, 256, 1, 1);

    // CSR build
    deg_zero_k<<<(Nn + 255) / 256, 256>>>(deg);
    deg_hist_k<<<(Ee + 255) / 256, 256>>>(dst, deg);
    scan_k<<<1, 1024>>>(deg, off, cur, nrm);
    fill_k<<<(Ee + 255) / 256, 256>>>(src, dst, nrm, cur, csrc, eid, coef);

    // 3 GCN layers: GEMM(hr -> hw logical), agg(hw -> lout logical, hr rotated)
    for (int l = 0; l < 3; l++) {
        mma_gemm_k<<<dim3(mtiles, 1), 512, SM>>>(
            hr, wt_g + (size_t)l * 65536, nullptr, hw, nullptr, Nn, 256, 256, 0, 0);
        float* lout = out_inter + (size_t)l * Nn * Hh;
        float* lout2 = (l == 2) ? out_h : nullptr;
        gcn_agg_k<<<nblocks, 256>>>(hw, off, csrc, coef, nrm, bg + (size_t)l * Hh,
                                    lout, hr, lout2);
    }

    // fused edge-MLP + perm-hidden GEMM: N=640 -> AB (cols 0..511), ph (512..639)
    mma_gemm_k<<<dim3(mtiles, 3), 512, SM>>>(hr, wt_hp, b640, AB, ph, Nn, 640, 512, 0, 0);
    edge_mlp_csr_k<<<nblocks, 256>>>(AB, off, csrc, eid, Wh2, bh2, out_hier);
    perm_k<<<nblocks, 256>>>(ph, Wp2, bp2, out_perm);
}